// round 15
// baseline (speedup 1.0000x reference)
#include <cuda_runtime.h>
#include <cuda_bf16.h>
#include <cstdint>

#define B_      4
#define CIN     256
#define HH      32
#define WW      88
#define HW      2816
#define PTOT    11264
#define COUT    128
#define OUTH    432
#define OUTW    496
#define XVEC    124             // 496/4
#define NPLANE  512
#define YTILE   54              // 432 = 8*54
#define NYT     8
#define SROWS   6
#define YHALF   27

#define KC      32              // k-chunk
#define PB      64              // positions per block
#define CB      64              // channels per block
#define KPAD    40              // bf16 per W smem row (80B, conflict-free ldsm)
#define PPAD    72              // bf16 per F smem row (144B, conflict-free ldsm)

__device__ float g_ctx[NPLANE * HW];

// ---------------------------------------------------------------------------
// mma / ldmatrix helpers
// ---------------------------------------------------------------------------
__device__ __forceinline__ void ldsm4(uint32_t* r, uint32_t a) {
    asm volatile("ldmatrix.sync.aligned.m8n8.x4.shared.b16 {%0,%1,%2,%3}, [%4];"
        : "=r"(r[0]), "=r"(r[1]), "=r"(r[2]), "=r"(r[3]) : "r"(a));
}
__device__ __forceinline__ void ldsm4t(uint32_t* r, uint32_t a) {
    asm volatile("ldmatrix.sync.aligned.m8n8.x4.trans.shared.b16 {%0,%1,%2,%3}, [%4];"
        : "=r"(r[0]), "=r"(r[1]), "=r"(r[2]), "=r"(r[3]) : "r"(a));
}
__device__ __forceinline__ void mma_bf16(float* d, const uint32_t* a,
                                         uint32_t b0, uint32_t b1) {
    asm volatile("mma.sync.aligned.m16n8k16.row.col.f32.bf16.bf16.f32 "
        "{%0,%1,%2,%3}, {%4,%5,%6,%7}, {%8,%9}, {%0,%1,%2,%3};"
        : "+f"(d[0]), "+f"(d[1]), "+f"(d[2]), "+f"(d[3])
        : "r"(a[0]), "r"(a[1]), "r"(a[2]), "r"(a[3]), "r"(b0), "r"(b1));
}

// split a float into bf16 hi + bf16 lo (residual)
__device__ __forceinline__ void bsplit(float v, __nv_bfloat16& hi, __nv_bfloat16& lo) {
    hi = __float2bfloat16_rn(v);
    lo = __float2bfloat16_rn(v - __bfloat162float(hi));
}

// ---------------------------------------------------------------------------
// Kernel 1: split-bf16 tensor-core GEMM (R14 proven, + pbase batch offset).
// ---------------------------------------------------------------------------
__global__ __launch_bounds__(128)
void lss_gemm_kernel(const float* __restrict__ feat,
                     const float* __restrict__ Wc,
                     const float* __restrict__ bc,
                     int pbase)
{
    __shared__ __align__(16) __nv_bfloat16 Whi[2][CB * KPAD];
    __shared__ __align__(16) __nv_bfloat16 Wlo[2][CB * KPAD];
    __shared__ __align__(16) __nv_bfloat16 Fhi[2][KC * PPAD];
    __shared__ __align__(16) __nv_bfloat16 Flo[2][KC * PPAD];

    const int tid   = threadIdx.x;
    const int p0    = pbase + blockIdx.x * PB;
    const int b     = p0 / HW;
    const int hw0   = p0 - b * HW;
    const int cbase = blockIdx.y * CB;          // 0 or 64

    const float4* feat4 = (const float4*)(feat + (size_t)b * CIN * HW + hw0); // row stride 704 f4

    const int lkk = tid >> 4;        // 0..7
    const int lcv = tid & 15;        // 0..15

    const int wcc = tid >> 3;        // 0..15  (c within pass)
    const int wkq = tid & 7;         // 0..7   (k float4-quad)
    const float* Wbase = Wc + (size_t)(64 + cbase + wcc) * CIN + wkq * 4;

    float4 wf[4], fr[4];

    auto load_regs = [&](int ch) {
        int k0 = ch * KC;
#pragma unroll
        for (int j = 0; j < 4; j++)
            wf[j] = *(const float4*)(Wbase + (size_t)(16 * j) * CIN + k0);
#pragma unroll
        for (int it = 0; it < 4; it++)
            fr[it] = feat4[(size_t)(k0 + lkk + it * 8) * 704 + lcv];
    };

    const float inv64 = 1.0f / 64.0f;

    auto store_chunk = [&](int buf) {
#pragma unroll
        for (int j = 0; j < 4; j++) {
            int cloc = wcc + 16 * j;
            __nv_bfloat162 h01, h23, l01, l23;
            bsplit(wf[j].x * inv64, h01.x, l01.x);
            bsplit(wf[j].y * inv64, h01.y, l01.y);
            bsplit(wf[j].z * inv64, h23.x, l23.x);
            bsplit(wf[j].w * inv64, h23.y, l23.y);
            uint2 hv, lv;
            hv.x = *(uint32_t*)&h01; hv.y = *(uint32_t*)&h23;
            lv.x = *(uint32_t*)&l01; lv.y = *(uint32_t*)&l23;
            int base = cloc * KPAD + wkq * 4;
            *(uint2*)&Whi[buf][base] = hv;
            *(uint2*)&Wlo[buf][base] = lv;
        }
#pragma unroll
        for (int it = 0; it < 4; it++) {
            int k = lkk + it * 8;
            float4 f = fr[it];
            __nv_bfloat162 h01, h23, l01, l23;
            bsplit(f.x, h01.x, l01.x);
            bsplit(f.y, h01.y, l01.y);
            bsplit(f.z, h23.x, l23.x);
            bsplit(f.w, h23.y, l23.y);
            uint2 hv, lv;
            hv.x = *(uint32_t*)&h01; hv.y = *(uint32_t*)&h23;
            lv.x = *(uint32_t*)&l01; lv.y = *(uint32_t*)&l23;
            int base = k * PPAD + 4 * lcv;
            *(uint2*)&Fhi[buf][base] = hv;
            *(uint2*)&Flo[buf][base] = lv;
        }
    };

    load_regs(0);
    store_chunk(0);
    __syncthreads();

    const int wid  = tid >> 5;
    const int lane = tid & 31;
    const int c0w  = wid * 16;

    float acc[8][4];
#pragma unroll
    for (int i = 0; i < 8; i++)
#pragma unroll
        for (int j = 0; j < 4; j++) acc[i][j] = 0.0f;

    const int a_row = c0w + (lane & 15);
    const int a_coff = (lane >> 4) << 3;                        // 0 or 8
    const int b_krow = (lane & 7) + (((lane >> 3) & 1) << 3);   // 0..15
    const int b_coff = (lane >> 4) << 3;                        // 0 or 8

    uint32_t whiB[2], wloB[2], fhiB[2], floB[2];
#pragma unroll
    for (int s = 0; s < 2; s++) {
        whiB[s] = (uint32_t)__cvta_generic_to_shared(Whi[s]);
        wloB[s] = (uint32_t)__cvta_generic_to_shared(Wlo[s]);
        fhiB[s] = (uint32_t)__cvta_generic_to_shared(Fhi[s]);
        floB[s] = (uint32_t)__cvta_generic_to_shared(Flo[s]);
    }

    int buf = 0;
    for (int ch = 0; ch < CIN / KC; ch++) {
        if (ch < CIN / KC - 1) load_regs(ch + 1);

#pragma unroll
        for (int ks = 0; ks < KC; ks += 16) {
            uint32_t ahi[4], alo[4];
            uint32_t aoff = (uint32_t)(a_row * KPAD + ks + a_coff) * 2;
            ldsm4(ahi, whiB[buf] + aoff);
            ldsm4(alo, wloB[buf] + aoff);
#pragma unroll
            for (int nt2 = 0; nt2 < 4; nt2++) {
                uint32_t bhi[4], blo[4];
                uint32_t boff = (uint32_t)((ks + b_krow) * PPAD + nt2 * 16 + b_coff) * 2;
                ldsm4t(bhi, fhiB[buf] + boff);
                ldsm4t(blo, floB[buf] + boff);
                int nt = nt2 * 2;
                mma_bf16(acc[nt],     ahi, bhi[0], bhi[1]);
                mma_bf16(acc[nt],     ahi, blo[0], blo[1]);
                mma_bf16(acc[nt],     alo, bhi[0], bhi[1]);
                mma_bf16(acc[nt + 1], ahi, bhi[2], bhi[3]);
                mma_bf16(acc[nt + 1], ahi, blo[2], blo[3]);
                mma_bf16(acc[nt + 1], alo, bhi[2], bhi[3]);
            }
        }

        if (ch < CIN / KC - 1) {
            store_chunk(buf ^ 1);
            __syncthreads();
            buf ^= 1;
        }
    }

    const int m0 = cbase + c0w + (lane >> 2);
    const int pb2 = 2 * (lane & 3);
    const float bia0 = bc[64 + m0] * inv64;
    const float bia1 = bc[64 + m0 + 8] * inv64;
    float* row0 = &g_ctx[((size_t)(b * COUT + m0)) * HW + hw0 + pb2];
    float* row1 = &g_ctx[((size_t)(b * COUT + m0 + 8)) * HW + hw0 + pb2];
#pragma unroll
    for (int nt = 0; nt < 8; nt++) {
        float2 v0 = make_float2(acc[nt][0] + bia0, acc[nt][1] + bia0);
        float2 v1 = make_float2(acc[nt][2] + bia1, acc[nt][3] + bia1);
        *(float2*)(row0 + nt * 8) = v0;
        *(float2*)(row1 + nt * 8) = v1;
    }
}

// ---------------------------------------------------------------------------
// Kernel 2: separable bilinear upsample (proven version, + plane offset).
// ---------------------------------------------------------------------------
__global__ __launch_bounds__(256)
void lss_upsample_kernel(float* __restrict__ out, int plane0)
{
    __shared__ float raw[SROWS][WW];
    __shared__ float hrow[SROWS][OUTW];
    __shared__ float ywy[YTILE];
    __shared__ int   yi0s[YTILE];

    const int tid   = threadIdx.x;
    const int t     = blockIdx.x;              // 0..7
    const int plane = plane0 + blockIdx.y;     // batch slice

    const float SY = 32.0f / 432.0f;
    const float OY = 16.0f / 432.0f - 0.5f;
    const float SX = 88.0f / 496.0f;
    const float OX = 44.0f / 496.0f - 0.5f;

    const int rbase = max(4 * t - 1, 0);

    if (tid < YTILE) {
        int Y = t * YTILE + tid;
        float fy = fminf(fmaxf((float)Y * SY + OY, 0.0f), 31.0f);
        int   y0 = (int)fy;
        ywy[tid]  = fy - (float)y0;
        yi0s[tid] = y0 - rbase;        // 0..4, monotone non-decreasing
    }

    // Phase A: load 6 source rows (edge-clamped)
    const float* cb = g_ctx + (size_t)plane * HW;
    for (int i = tid; i < SROWS * WW; i += 256) {
        int r = i / WW, x = i - r * WW;
        int ry = min(rbase + r, HH - 1);
        raw[r][x] = cb[ry * WW + x];
    }
    __syncthreads();

    // Phase B: horizontal interpolation
    for (int i = tid; i < SROWS * 512; i += 256) {
        int r = i >> 9, X = i & 511;
        if (X < OUTW) {
            float fx = fminf(fmaxf((float)X * SX + OX, 0.0f), 87.0f);
            int   x0 = (int)fx;
            float wx = fx - (float)x0;
            int   x1 = min(x0 + 1, WW - 1);
            float a = raw[r][x0];
            hrow[r][X] = fmaf(wx, raw[r][x1] - a, a);
        }
    }
    __syncthreads();

    // Phase C: vertical pass. Two 124-thread halves each cover 27 rows.
    const int half = tid >> 7;         // 0 or 1
    const int lx   = tid & 127;        // x-column within half
    if (lx < XVEC) {
        const int xo    = lx << 2;
        const int ybeg  = half * YHALF;
        const int yend  = ybeg + YHALF;
        float4* orow = (float4*)out + (size_t)plane * OUTH * XVEC
                       + (size_t)(t * YTILE + ybeg) * XVEC + lx;
        int yy = ybeg;
        const int r0 = yi0s[ybeg];
#pragma unroll
        for (int r = 0; r < 5; r++) {
            if (r >= r0 && yy < yend && yi0s[yy] == r) {
                float4 a = *(const float4*)&hrow[r][xo];
                float4 b = *(const float4*)&hrow[r + 1][xo];
                float4 d;
                d.x = b.x - a.x; d.y = b.y - a.y; d.z = b.z - a.z; d.w = b.w - a.w;
                do {
                    float wy = ywy[yy];
                    float4 o;
                    o.x = fmaf(wy, d.x, a.x);
                    o.y = fmaf(wy, d.y, a.y);
                    o.z = fmaf(wy, d.z, a.z);
                    o.w = fmaf(wy, d.w, a.w);
                    __stcs(orow, o);
                    orow += XVEC;
                    yy++;
                } while (yy < yend && yi0s[yy] == r);
            }
        }
    }
}

// ---------------------------------------------------------------------------
// Launcher: per-batch pipeline. GEMM batches back-to-back on the main stream;
// each batch's upsample on a forked stream gated by an event, joined at end.
// Only kernel launches + event edges — graph-capturable. No device allocs.
// ---------------------------------------------------------------------------
extern "C" void kernel_launch(void* const* d_in, const int* in_sizes, int n_in,
                              void* d_out, int out_size)
{
    const float* feat = (const float*)d_in[0];
    const float* Wc   = (const float*)d_in[1];
    const float* bc   = (const float*)d_in[2];
    float* out        = (float*)d_out;

    cudaStream_t s2;
    cudaStreamCreateWithFlags(&s2, cudaStreamNonBlocking);
    cudaEvent_t eg[B_], ej;
    for (int i = 0; i < B_; i++)
        cudaEventCreateWithFlags(&eg[i], cudaEventDisableTiming);
    cudaEventCreateWithFlags(&ej, cudaEventDisableTiming);

    for (int b = 0; b < B_; b++) {
        dim3 gg(HW / PB, 2);               // 44 x 2 blocks per batch
        lss_gemm_kernel<<<gg, 128>>>(feat, Wc, bc, b * HW);
        cudaEventRecord(eg[b], 0);
        cudaStreamWaitEvent(s2, eg[b], 0);
        dim3 ug(NYT, COUT);                // 8 x 128 planes per batch
        lss_upsample_kernel<<<ug, 256, 0, s2>>>(out, b * COUT);
    }
    cudaEventRecord(ej, s2);
    cudaStreamWaitEvent(0, ej, 0);
}

// round 16
// speedup vs baseline: 1.5686x; 1.5686x over previous
#include <cuda_runtime.h>
#include <cuda_fp16.h>
#include <cstdint>

#define B_      4
#define CIN     256
#define HH      32
#define WW      88
#define HW      2816
#define PTOT    11264
#define COUT    128
#define OUTH    432
#define OUTW    496
#define XVEC    124             // 496/4
#define NPLANE  512
#define YTILE   54              // 432 = 8*54
#define NYT     8
#define SROWS   6
#define YHALF   27

#define KC      32              // k-chunk
#define PB      64              // positions per block
#define CB      64              // channels per block
#define KPAD    40              // f16 per W smem row (80B, conflict-free ldsm)
#define PPAD    72              // f16 per F smem row (144B, conflict-free ldsm)

__device__ float g_ctx[NPLANE * HW];

// ---------------------------------------------------------------------------
// mma / ldmatrix helpers
// ---------------------------------------------------------------------------
__device__ __forceinline__ void ldsm4(uint32_t* r, uint32_t a) {
    asm volatile("ldmatrix.sync.aligned.m8n8.x4.shared.b16 {%0,%1,%2,%3}, [%4];"
        : "=r"(r[0]), "=r"(r[1]), "=r"(r[2]), "=r"(r[3]) : "r"(a));
}
__device__ __forceinline__ void ldsm4t(uint32_t* r, uint32_t a) {
    asm volatile("ldmatrix.sync.aligned.m8n8.x4.trans.shared.b16 {%0,%1,%2,%3}, [%4];"
        : "=r"(r[0]), "=r"(r[1]), "=r"(r[2]), "=r"(r[3]) : "r"(a));
}
__device__ __forceinline__ void mma_f16(float* d, const uint32_t* a,
                                        uint32_t b0, uint32_t b1) {
    asm volatile("mma.sync.aligned.m16n8k16.row.col.f32.f16.f16.f32 "
        "{%0,%1,%2,%3}, {%4,%5,%6,%7}, {%8,%9}, {%0,%1,%2,%3};"
        : "+f"(d[0]), "+f"(d[1]), "+f"(d[2]), "+f"(d[3])
        : "r"(a[0]), "r"(a[1]), "r"(a[2]), "r"(a[3]), "r"(b0), "r"(b1));
}

// split a float into f16 hi + f16 lo (residual)
__device__ __forceinline__ void hsplit(float v, __half& hi, __half& lo) {
    hi = __float2half_rn(v);
    lo = __float2half_rn(v - __half2float(hi));
}

// ---------------------------------------------------------------------------
// Kernel 1: fp16 tensor-core GEMM. W split hi+lo (exact to ~2^-22),
// F single fp16 (rounding 2^-11 -> global rel_err ~3e-4).
// Block 64c x 64p, 128 threads (4 warps). Warp w: m-tile = channels w*16..+15,
// 8 n8-tiles over 64 positions. KC=32 double-buffered.
// acc += (Whi + Wlo) * Fhi ; scale by 1/64 + bias in epilogue.
// ---------------------------------------------------------------------------
__global__ __launch_bounds__(128)
void lss_gemm_kernel(const float* __restrict__ feat,
                     const float* __restrict__ Wc,
                     const float* __restrict__ bc)
{
    __shared__ __align__(16) __half Whi[2][CB * KPAD];
    __shared__ __align__(16) __half Wlo[2][CB * KPAD];
    __shared__ __align__(16) __half Fhi[2][KC * PPAD];

    const int tid   = threadIdx.x;
    const int p0    = blockIdx.x * PB;
    const int b     = p0 / HW;
    const int hw0   = p0 - b * HW;
    const int cbase = blockIdx.y * CB;          // 0 or 64

    const float4* feat4 = (const float4*)(feat + (size_t)b * CIN * HW + hw0); // row stride 704 f4

    // F loader mapping (proven)
    const int lkk = tid >> 4;        // 0..7
    const int lcv = tid & 15;        // 0..15

    // W loader mapping: 4 passes, each pass 16 c-rows x 8 k-quads
    const int wcc = tid >> 3;        // 0..15  (c within pass)
    const int wkq = tid & 7;         // 0..7   (k float4-quad)
    const float* Wbase = Wc + (size_t)(64 + cbase + wcc) * CIN + wkq * 4;

    float4 wf[4], fr[4];

    auto load_regs = [&](int ch) {
        int k0 = ch * KC;
#pragma unroll
        for (int j = 0; j < 4; j++)
            wf[j] = *(const float4*)(Wbase + (size_t)(16 * j) * CIN + k0);
#pragma unroll
        for (int it = 0; it < 4; it++)
            fr[it] = feat4[(size_t)(k0 + lkk + it * 8) * 704 + lcv];
    };

    auto store_chunk = [&](int buf) {
#pragma unroll
        for (int j = 0; j < 4; j++) {
            int cloc = wcc + 16 * j;
            __half2 h01, h23, l01, l23;
            hsplit(wf[j].x, h01.x, l01.x);
            hsplit(wf[j].y, h01.y, l01.y);
            hsplit(wf[j].z, h23.x, l23.x);
            hsplit(wf[j].w, h23.y, l23.y);
            uint2 hv, lv;
            hv.x = *(uint32_t*)&h01; hv.y = *(uint32_t*)&h23;
            lv.x = *(uint32_t*)&l01; lv.y = *(uint32_t*)&l23;
            int base = cloc * KPAD + wkq * 4;     // f16 units, 8B aligned
            *(uint2*)&Whi[buf][base] = hv;
            *(uint2*)&Wlo[buf][base] = lv;
        }
#pragma unroll
        for (int it = 0; it < 4; it++) {
            int k = lkk + it * 8;
            float4 f = fr[it];
            __half2 h01 = __floats2half2_rn(f.x, f.y);
            __half2 h23 = __floats2half2_rn(f.z, f.w);
            uint2 hv;
            hv.x = *(uint32_t*)&h01; hv.y = *(uint32_t*)&h23;
            int base = k * PPAD + 4 * lcv;        // f16 units, 8B aligned
            *(uint2*)&Fhi[buf][base] = hv;
        }
    };

    load_regs(0);
    store_chunk(0);
    __syncthreads();

    const int wid  = tid >> 5;
    const int lane = tid & 31;
    const int c0w  = wid * 16;

    float acc[8][4];
#pragma unroll
    for (int i = 0; i < 8; i++)
#pragma unroll
        for (int j = 0; j < 4; j++) acc[i][j] = 0.0f;

    // per-lane ldmatrix row/col components (constant across chunks)
    const int a_row = c0w + (lane & 15);
    const int a_coff = (lane >> 4) << 3;                        // 0 or 8
    const int b_krow = (lane & 7) + (((lane >> 3) & 1) << 3);   // 0..15
    const int b_coff = (lane >> 4) << 3;                        // 0 or 8

    uint32_t whiB[2], wloB[2], fhiB[2];
#pragma unroll
    for (int s = 0; s < 2; s++) {
        whiB[s] = (uint32_t)__cvta_generic_to_shared(Whi[s]);
        wloB[s] = (uint32_t)__cvta_generic_to_shared(Wlo[s]);
        fhiB[s] = (uint32_t)__cvta_generic_to_shared(Fhi[s]);
    }

    int buf = 0;
    for (int ch = 0; ch < CIN / KC; ch++) {
        if (ch < CIN / KC - 1) load_regs(ch + 1);

#pragma unroll
        for (int ks = 0; ks < KC; ks += 16) {
            uint32_t ahi[4], alo[4];
            uint32_t aoff = (uint32_t)(a_row * KPAD + ks + a_coff) * 2;
            ldsm4(ahi, whiB[buf] + aoff);
            ldsm4(alo, wloB[buf] + aoff);
#pragma unroll
            for (int nt2 = 0; nt2 < 4; nt2++) {
                uint32_t bb[4];
                uint32_t boff = (uint32_t)((ks + b_krow) * PPAD + nt2 * 16 + b_coff) * 2;
                ldsm4t(bb, fhiB[buf] + boff);
                int nt = nt2 * 2;
                mma_f16(acc[nt],     ahi, bb[0], bb[1]);
                mma_f16(acc[nt],     alo, bb[0], bb[1]);
                mma_f16(acc[nt + 1], ahi, bb[2], bb[3]);
                mma_f16(acc[nt + 1], alo, bb[2], bb[3]);
            }
        }

        if (ch < CIN / KC - 1) {
            store_chunk(buf ^ 1);
            __syncthreads();
            buf ^= 1;
        }
    }

    // Epilogue: D[m][n] lane map: d0:(m=lane>>2, n=2*(lane&3)), d1:n+1,
    // d2:(m+8,n), d3:(m+8,n+1). Scale acc by 1/64 here (W was unscaled).
    const float inv64 = 1.0f / 64.0f;
    const int m0 = cbase + c0w + (lane >> 2);
    const int pb2 = 2 * (lane & 3);
    const float bia0 = bc[64 + m0] * inv64;
    const float bia1 = bc[64 + m0 + 8] * inv64;
    float* row0 = &g_ctx[((size_t)(b * COUT + m0)) * HW + hw0 + pb2];
    float* row1 = &g_ctx[((size_t)(b * COUT + m0 + 8)) * HW + hw0 + pb2];
#pragma unroll
    for (int nt = 0; nt < 8; nt++) {
        float2 v0 = make_float2(fmaf(acc[nt][0], inv64, bia0),
                                fmaf(acc[nt][1], inv64, bia0));
        float2 v1 = make_float2(fmaf(acc[nt][2], inv64, bia1),
                                fmaf(acc[nt][3], inv64, bia1));
        *(float2*)(row0 + nt * 8) = v0;
        *(float2*)(row1 + nt * 8) = v1;
    }
}

// ---------------------------------------------------------------------------
// Kernel 2: separable bilinear upsample (proven version, unchanged).
// ---------------------------------------------------------------------------
__global__ __launch_bounds__(256)
void lss_upsample_kernel(float* __restrict__ out)
{
    __shared__ float raw[SROWS][WW];
    __shared__ float hrow[SROWS][OUTW];
    __shared__ float ywy[YTILE];
    __shared__ int   yi0s[YTILE];

    const int tid   = threadIdx.x;
    const int t     = blockIdx.x;      // 0..7
    const int plane = blockIdx.y;      // 0..511

    const float SY = 32.0f / 432.0f;
    const float OY = 16.0f / 432.0f - 0.5f;
    const float SX = 88.0f / 496.0f;
    const float OX = 44.0f / 496.0f - 0.5f;

    const int rbase = max(4 * t - 1, 0);

    if (tid < YTILE) {
        int Y = t * YTILE + tid;
        float fy = fminf(fmaxf((float)Y * SY + OY, 0.0f), 31.0f);
        int   y0 = (int)fy;
        ywy[tid]  = fy - (float)y0;
        yi0s[tid] = y0 - rbase;        // 0..4, monotone non-decreasing
    }

    // Phase A: load 6 source rows (edge-clamped)
    const float* cb = g_ctx + (size_t)plane * HW;
    for (int i = tid; i < SROWS * WW; i += 256) {
        int r = i / WW, x = i - r * WW;
        int ry = min(rbase + r, HH - 1);
        raw[r][x] = cb[ry * WW + x];
    }
    __syncthreads();

    // Phase B: horizontal interpolation
    for (int i = tid; i < SROWS * 512; i += 256) {
        int r = i >> 9, X = i & 511;
        if (X < OUTW) {
            float fx = fminf(fmaxf((float)X * SX + OX, 0.0f), 87.0f);
            int   x0 = (int)fx;
            float wx = fx - (float)x0;
            int   x1 = min(x0 + 1, WW - 1);
            float a = raw[r][x0];
            hrow[r][X] = fmaf(wx, raw[r][x1] - a, a);
        }
    }
    __syncthreads();

    // Phase C: vertical pass. Two 124-thread halves each cover 27 rows.
    const int half = tid >> 7;         // 0 or 1
    const int lx   = tid & 127;        // x-column within half
    if (lx < XVEC) {
        const int xo    = lx << 2;
        const int ybeg  = half * YHALF;
        const int yend  = ybeg + YHALF;
        float4* orow = (float4*)out + (size_t)plane * OUTH * XVEC
                       + (size_t)(t * YTILE + ybeg) * XVEC + lx;
        int yy = ybeg;
        const int r0 = yi0s[ybeg];
#pragma unroll
        for (int r = 0; r < 5; r++) {
            if (r >= r0 && yy < yend && yi0s[yy] == r) {
                float4 a = *(const float4*)&hrow[r][xo];
                float4 b = *(const float4*)&hrow[r + 1][xo];
                float4 d;
                d.x = b.x - a.x; d.y = b.y - a.y; d.z = b.z - a.z; d.w = b.w - a.w;
                do {
                    float wy = ywy[yy];
                    float4 o;
                    o.x = fmaf(wy, d.x, a.x);
                    o.y = fmaf(wy, d.y, a.y);
                    o.z = fmaf(wy, d.z, a.z);
                    o.w = fmaf(wy, d.w, a.w);
                    __stcs(orow, o);
                    orow += XVEC;
                    yy++;
                } while (yy < yend && yi0s[yy] == r);
            }
        }
    }
}

extern "C" void kernel_launch(void* const* d_in, const int* in_sizes, int n_in,
                              void* d_out, int out_size)
{
    const float* feat = (const float*)d_in[0];
    const float* Wc   = (const float*)d_in[1];
    const float* bc   = (const float*)d_in[2];
    float* out        = (float*)d_out;

    dim3 ggrid(PTOT / PB, 2);
    lss_gemm_kernel<<<ggrid, 128>>>(feat, Wc, bc);

    dim3 ugrid(NYT, NPLANE);
    lss_upsample_kernel<<<ugrid, 256>>>(out);
}